// round 9
// baseline (speedup 1.0000x reference)
#include <cuda_runtime.h>
#include <cuda_bf16.h>
#include <cuda_fp16.h>
#include <cstdint>

// Problem constants (fixed by the reference)
#define NVOX   131072
#define KVOL   27
#define PPK    65536
#define CIN    64
#define COUT   64
#define NTHREADS 128

// ---------------------------------------------------------------------------
// Pre-converted fp16 operands (built once by prep kernels):
//   g_in : in_feats as fp16, [NVOX][CIN]  (16 MB, rows are 128B = 1 line)
//   g_Wh : weights as fp16, transposed + column-permuted [KVOL][64 phys n][CIN]
// Physical row p = 8j + c holds logical cout n = 16*(j>>1)+4*(c>>1)+2*(j&1)+(c&1)
// -> each MMA thread's 4 values from a tile pair cover 4 consecutive couts
//    (red.v4 epilogue straight from fragments).
// ---------------------------------------------------------------------------
__device__ __half g_in[NVOX * CIN];
__device__ __half g_Wh[KVOL * COUT * CIN];

// smem: fp16 tiles, 128B per logical row, XOR-swizzled 16B chunks
#define SM_A     0                         // 128 rows x 128B = 16384
#define SM_B     16384                     // 64 rows x 128B = 8192
#define SM_TOTAL 24576

// ---------------------------------------------------------------------------
// PTX helpers (family-portable: ldmatrix sm_75+, mma fp16 sm_70+, red sm_90)
// ---------------------------------------------------------------------------
__device__ __forceinline__ uint32_t smem_u32(const void* p) {
    uint32_t a;
    asm("{ .reg .u64 t; cvta.to.shared.u64 t, %1; cvt.u32.u64 %0, t; }" : "=r"(a) : "l"(p));
    return a;
}

__device__ __forceinline__ void ldsm_x4(uint32_t r[4], uint32_t addr) {
    asm volatile("ldmatrix.sync.aligned.m8n8.x4.shared.b16 {%0,%1,%2,%3}, [%4];"
                 : "=r"(r[0]), "=r"(r[1]), "=r"(r[2]), "=r"(r[3]) : "r"(addr));
}

__device__ __forceinline__ void mma_fp16(float d[4], const uint32_t a[4], const uint32_t b[2]) {
    asm volatile(
        "mma.sync.aligned.m16n8k16.row.col.f32.f16.f16.f32 "
        "{%0,%1,%2,%3}, {%4,%5,%6,%7}, {%8,%9}, {%0,%1,%2,%3};"
        : "+f"(d[0]), "+f"(d[1]), "+f"(d[2]), "+f"(d[3])
        : "r"(a[0]), "r"(a[1]), "r"(a[2]), "r"(a[3]), "r"(b[0]), "r"(b[1]));
}

__device__ __forceinline__ void red_add_v4(float* addr, float a, float b, float c, float d) {
    asm volatile("red.global.add.v4.f32 [%0], {%1, %2, %3, %4};"
                 :: "l"(addr), "f"(a), "f"(b), "f"(c), "f"(d) : "memory");
}

// ---------------------------------------------------------------------------
// Kernel 1: out[n][c] = bias[c]
// ---------------------------------------------------------------------------
__global__ void init_bias_kernel(float4* __restrict__ out, const float4* __restrict__ bias) {
    int i = blockIdx.x * blockDim.x + threadIdx.x;
    out[i] = bias[i & 15];
}

// ---------------------------------------------------------------------------
// Kernel 2a: in_feats -> fp16 (one float4 -> 8B per thread)
// ---------------------------------------------------------------------------
__global__ void prep_in_kernel(const float4* __restrict__ in_feats) {
    const int i = blockIdx.x * blockDim.x + threadIdx.x;   // float4 index
    float4 v = in_feats[i];
    __half2 h01 = make_half2(__float2half_rn(v.x), __float2half_rn(v.y));
    __half2 h23 = make_half2(__float2half_rn(v.z), __float2half_rn(v.w));
    uint2 hv;
    hv.x = *(uint32_t*)&h01;  hv.y = *(uint32_t*)&h23;
    *(uint2*)(g_in + 4 * (size_t)i) = hv;
}

// ---------------------------------------------------------------------------
// Kernel 2b: weights -> fp16, transposed + column-permuted
// ---------------------------------------------------------------------------
__global__ void prep_weights_kernel(const float* __restrict__ weights) {
    const int koff = blockIdx.x;
    const float* W = weights + (size_t)koff * CIN * COUT;
    __half* wh = g_Wh + (size_t)koff * COUT * CIN;
    for (int o = threadIdx.x; o < COUT * CIN; o += blockDim.x) {
        const int p = o >> 6, kk = o & 63;
        const int j = p >> 3, c = p & 7;
        const int n = 16 * (j >> 1) + 4 * (c >> 1) + 2 * (j & 1) + (c & 1);
        wh[o] = __float2half_rn(W[kk * COUT + n]);   // transpose + permute
    }
}

// ---------------------------------------------------------------------------
// Kernel 3: fp16 HMMA GEMM-scatter. One block per (k offset, 128-pair tile).
//   D[128p x 64n] = A_fp16 * B_fp16  (fp32 register accum; single pass)
// ---------------------------------------------------------------------------
__global__ __launch_bounds__(NTHREADS, 4) void conv3d_tc_kernel(
    const int*   __restrict__ imap,       // [KVOL, PPK]
    const int*   __restrict__ omap,       // [KVOL, PPK]
    float*       __restrict__ out)        // [NVOX, COUT]
{
    extern __shared__ __align__(128) char smem[];
    const uint32_t smem_base = smem_u32(smem);
    const int tid = threadIdx.x;
    const int w = tid >> 5, l = tid & 31;
    const int k  = blockIdx.y;
    const int p0 = blockIdx.x * 128;

    // ---- B staging: 8KB fp16 tile [phys n][k], swizzled 16B chunks ----
    {
        const uint4* bh = (const uint4*)(g_Wh + (size_t)k * COUT * CIN);
        #pragma unroll
        for (int i = 0; i < 4; i++) {
            const int u = tid + i * NTHREADS;          // 16B unit 0..511
            const int n = u >> 3, c = u & 7;
            const uint32_t off = n * 128 + ((c ^ (n & 7)) << 4);
            *(uint4*)(smem + SM_B + off) = bh[u];
        }
    }

    // ---- A staging: fp16 gather, 1 line per row, direct swizzled STS ----
    // Lane l covers chunk (l&7) of row-sub (l>>3); 4 rows per warp-instr.
    {
        const int myidx = imap[k * PPK + p0 + w * 32 + l];
        const int chunk = l & 7, rsub = l >> 3;
        #pragma unroll
        for (int q = 0; q < 8; q++) {
            const int src = __shfl_sync(0xffffffffu, myidx, q * 4 + rsub);
            const int r = w * 32 + q * 4 + rsub;
            uint4 v = *(const uint4*)(g_in + (size_t)src * CIN + chunk * 8);
            const uint32_t off = r * 128 + ((chunk ^ (r & 7)) << 4);
            *(uint4*)(smem + SM_A + off) = v;
        }
    }

    // ---- prefetch omap rows (hidden behind MMA work) ----
    const int gid = l >> 2, tig = l & 3;
    int orow[2][2];
    {
        const int obase = k * PPK + p0 + w * 32 + gid;
        #pragma unroll
        for (int t = 0; t < 2; t++)
            #pragma unroll
            for (int h = 0; h < 2; h++)
                orow[t][h] = __ldg(omap + obase + 16 * t + 8 * h);
    }

    __syncthreads();

    // ---- per-lane ldmatrix address components ----
    const int lr = l & 7;
    const int rA  = w * 32 + ((l >> 3) & 1) * 8 + lr;  // A row for t=0 (+16 for t=1)
    const int gA  = l >> 4;                            // A kc offset 0/1
    const int sA  = rA & 7;
    const int nB  = 8 * (l >> 4) + lr;                 // B row for jj base (+16*jj)
    const int gB  = (l >> 3) & 1;                      // B kc offset 0/1
    const int sB  = nB & 7;

    float d[2][8][4];
    #pragma unroll
    for (int t = 0; t < 2; t++)
        #pragma unroll
        for (int j = 0; j < 8; j++)
            #pragma unroll
            for (int x = 0; x < 4; x++)
                d[t][j][x] = 0.0f;

    // ---- main loop over K (4 x k16 steps), single fp16 pass ----
    #pragma unroll
    for (int ks = 0; ks < 4; ks++) {
        const int kcA = 2 * ks + gA;
        const int kcB = 2 * ks + gB;
        const uint32_t offA  = rA * 128 + ((kcA ^ sA) << 4);
        const uint32_t offB0 = nB * 128 + ((kcB ^ sB) << 4);

        uint32_t a[2][4];
        ldsm_x4(a[0], smem_base + SM_A + offA);
        ldsm_x4(a[1], smem_base + SM_A + offA + 16 * 128);

        uint32_t b[8][2];
        #pragma unroll
        for (int jj = 0; jj < 4; jj++) {
            uint32_t rr[4];
            ldsm_x4(rr, smem_base + SM_B + offB0 + jj * 16 * 128);
            b[2 * jj][0] = rr[0]; b[2 * jj][1] = rr[1];
            b[2 * jj + 1][0] = rr[2]; b[2 * jj + 1][1] = rr[3];
        }

        #pragma unroll
        for (int t = 0; t < 2; t++)
            #pragma unroll
            for (int j = 0; j < 8; j++)
                mma_fp16(d[t][j], a[t], b[j]);
    }

    // ---- scatter-add epilogue: red.v4 straight from fragments ----
    #pragma unroll
    for (int t = 0; t < 2; t++) {
        #pragma unroll
        for (int h = 0; h < 2; h++) {
            float* dst = out + (size_t)orow[t][h] * COUT + 4 * tig;
            #pragma unroll
            for (int jp = 0; jp < 4; jp++)
                red_add_v4(dst + 16 * jp,
                           d[t][2 * jp][2 * h],     d[t][2 * jp][2 * h + 1],
                           d[t][2 * jp + 1][2 * h], d[t][2 * jp + 1][2 * h + 1]);
        }
    }
}

// ---------------------------------------------------------------------------
extern "C" void kernel_launch(void* const* d_in, const int* in_sizes, int n_in,
                              void* d_out, int out_size) {
    const float* in_feats = (const float*)d_in[0];
    const float* weights  = (const float*)d_in[1];
    const float* bias     = (const float*)d_in[2];
    const int*   imap     = (const int*)d_in[3];
    const int*   omap     = (const int*)d_in[4];
    float*       out      = (float*)d_out;

    cudaFuncSetAttribute(conv3d_tc_kernel,
                         cudaFuncAttributeMaxDynamicSharedMemorySize, SM_TOTAL);

    {
        const int total4 = NVOX * COUT / 4;
        init_bias_kernel<<<total4 / 256, 256>>>((float4*)out, (const float4*)bias);
    }

    prep_in_kernel<<<NVOX * CIN / 4 / 256, 256>>>((const float4*)in_feats);
    prep_weights_kernel<<<KVOL, 256>>>(weights);

    dim3 grid(PPK / 128, KVOL);
    conv3d_tc_kernel<<<grid, NTHREADS, SM_TOTAL>>>(imap, omap, out);
}